// round 1
// baseline (speedup 1.0000x reference)
#include <cuda_runtime.h>

#define NB 128   // persistent CTAs (<= 148 SMs -> all resident, spin barrier safe)
#define NT 256   // threads per CTA (8 warps)
#define TT 2048  // timesteps
#define BB 8     // batch
#define HD 512   // hidden

// ---------------- device scratch (no cudaMalloc allowed) ----------------
__device__ float g_h1[BB * TT * HD];      // layer-0 hidden sequence (33.5 MB)
__device__ float g_hbuf[2 * BB * HD];     // double-buffered h(t) broadcast
__device__ unsigned g_count;
__device__ volatile unsigned g_gen;

__global__ void reset_bar_kernel() { g_count = 0u; g_gen = 0u; }

__device__ __forceinline__ float sigm(float x) { return 1.0f / (1.0f + __expf(-x)); }

// Grid-wide barrier: monotonic generation counter. All NB CTAs are resident by
// construction (1 CTA/SM), so spinning is safe. threadfence (membar.gl +
// CCTL.IVALL on sm_103a) gives the cross-SM visibility we need for g_hbuf.
__device__ __forceinline__ void grid_bar(unsigned target) {
    __syncthreads();
    if (threadIdx.x == 0) {
        __threadfence();
        unsigned old = atomicAdd(&g_count, 1u);
        if (old == target * NB - 1u) {
            __threadfence();
            g_gen = target;
        } else {
            while (g_gen < target) { }
        }
    }
    __syncthreads();
}

// One K-partition of the gate matmul for this warp's gate group g:
// acc[r*8+b] += sum_k mat[(g*4+r)*KP + k] * src[b*KP + k], k-split 32 lanes x vec4.
template <int KP>
__device__ __forceinline__ void dot_part(float* acc, const float* __restrict__ mat,
                                         const float* __restrict__ src, int g, int lane) {
#pragma unroll
    for (int it = 0; it < KP / 128; it++) {
        const int kb = it * 128 + lane * 4;
        float4 m[4];
#pragma unroll
        for (int r = 0; r < 4; r++)
            m[r] = *(const float4*)(mat + (g * 4 + r) * KP + kb);
#pragma unroll
        for (int b = 0; b < 8; b++) {
            float4 v = *(const float4*)(src + b * KP + kb);
#pragma unroll
            for (int r = 0; r < 4; r++) {
                float a = acc[r * 8 + b];
                a = __fmaf_rn(m[r].x, v.x, a);
                a = __fmaf_rn(m[r].y, v.y, a);
                a = __fmaf_rn(m[r].z, v.z, a);
                a = __fmaf_rn(m[r].w, v.w, a);
                acc[r * 8 + b] = a;
            }
        }
    }
}

// Persistent LSTM layer kernel. CTA owns hidden columns [j0, j0+4) for all 4
// gates and all 8 batches. U/W slices live in shared for the whole sequence.
template <int DIN>
__global__ void __launch_bounds__(NT, 1) lstm_layer_kernel(
    const float* __restrict__ xin,   // [B, T, DIN] layer input
    const float* __restrict__ uW,    // [4H, H]
    const float* __restrict__ wW,    // [4H, DIN]
    const float* __restrict__ ub,    // [4H]
    const float* __restrict__ wb,    // [4H]
    float* __restrict__ hseq,        // [B, T, H] hidden sequence out
    float* __restrict__ hhout,       // [B, H] final h
    float* __restrict__ ccout)       // [B, H] final c
{
    extern __shared__ float sm[];
    float* sU     = sm;                    // 16 * HD
    float* sW     = sU + 16 * HD;          // 16 * DIN
    float* sIn    = sW + 16 * DIN;         // BB * DIN
    float* sH     = sIn + BB * DIN;        // BB * HD
    float* sPart  = sH + BB * HD;          // 128
    float* sGates = sPart + 128;           // 128
    float* sBias  = sGates + 128;          // 16
    float* sC     = sBias + 16;            // 32 (persistent cell state)

    const int tid  = threadIdx.x;
    const int j0   = blockIdx.x * 4;
    const int w    = tid >> 5;
    const int lane = tid & 31;
    const int g    = w & 3;    // gate group (i,f,g,o)
    const int part = w >> 2;   // 0: recurrent (U,h)  1: input (W,x)

    // ---- load resident weight slices ----
    for (int idx = tid; idx < 16 * HD; idx += NT) {
        int r = idx >> 9, k = idx & (HD - 1);
        sU[idx] = uW[((r >> 2) * HD + j0 + (r & 3)) * HD + k];
    }
    for (int idx = tid; idx < 16 * DIN; idx += NT) {
        int r = idx / DIN, k = idx % DIN;
        sW[idx] = wW[((r >> 2) * HD + j0 + (r & 3)) * DIN + k];
    }
    if (tid < 16) {
        int row = (tid >> 2) * HD + j0 + (tid & 3);
        sBias[tid] = ub[row] + wb[row];
    }
    if (tid < 32) {
        sC[tid] = 0.0f;
        int jl = tid >> 3, b = tid & 7;
        g_hbuf[b * HD + j0 + jl] = 0.0f;   // h(-1) = 0 in buffer 0
    }
    grid_bar(1);

    for (int t = 0; t < TT; t++) {
        // ---- stage h(t-1) and x_t into shared ----
        {
            const float4* hb4 = (const float4*)(g_hbuf + (t & 1) * BB * HD);
            float4* sH4 = (float4*)sH;
            for (int i = tid; i < BB * HD / 4; i += NT) sH4[i] = __ldcg(hb4 + i);
            const float4* in4 = (const float4*)xin;
            float4* sIn4 = (float4*)sIn;
            const int DV = DIN / 4;
            for (int i = tid; i < BB * DV; i += NT) {
                int b = i / DV, d = i - b * DV;
                sIn4[i] = in4[(b * TT + t) * DV + d];
            }
        }
        __syncthreads();

        // ---- gate dot products (register tile 4 rows x 8 batch, k-split 32) ----
        float acc[32];
#pragma unroll
        for (int j = 0; j < 32; j++) acc[j] = 0.0f;
        if (part == 0) dot_part<HD>(acc, sU, sH, g, lane);
        else           dot_part<DIN>(acc, sW, sIn, g, lane);

        // ---- reduce-scatter: 31 shuffles, lane l ends owning total of acc[l] ----
#pragma unroll
        for (int m = 16; m > 0; m >>= 1) {
            const bool hi = (lane & m) != 0;
#pragma unroll
            for (int j = 0; j < m; j++) {
                float sendv = hi ? acc[j] : acc[j + m];
                float other = __shfl_xor_sync(0xffffffffu, sendv, m);
                acc[j] = (hi ? acc[j + m] : acc[j]) + other;
            }
        }
        const float val = acc[0];   // lane's owned (jl,b) partial for gate g

        if (part == 0) sPart[g * 32 + lane] = val;
        __syncthreads();
        if (part == 1)
            sGates[g * 32 + lane] = val + sPart[g * 32 + lane] + sBias[g * 4 + (lane >> 3)];
        __syncthreads();

        // ---- cell update + writes (warp 0; lane = jl*8 + b) ----
        if (tid < 32) {
            const int jl = tid >> 3, b = tid & 7;
            const int jg = j0 + jl;
            float iv = sigm(sGates[tid]);
            float fv = sigm(sGates[32 + tid]);
            float gv = tanhf(sGates[64 + tid]);
            float ov = sigm(sGates[96 + tid]);
            float c = fv * sC[tid] + iv * gv;
            sC[tid] = c;
            float h = ov * fmaxf(c, 0.0f);   // custom relu nonlinearity
            g_hbuf[((t + 1) & 1) * BB * HD + b * HD + jg] = h;
            hseq[(b * TT + t) * HD + jg] = h;
            if (t == TT - 1) { hhout[b * HD + jg] = h; ccout[b * HD + jg] = c; }
        }
        grid_bar((unsigned)(t + 2));
    }
}

// ---------------- host launch ----------------
extern "C" void kernel_launch(void* const* d_in, const int* in_sizes, int n_in,
                              void* d_out, int out_size) {
    (void)in_sizes; (void)n_in; (void)out_size;
    const float* x   = (const float*)d_in[0];
    const float* w0w = (const float*)d_in[1];
    const float* w0b = (const float*)d_in[2];
    const float* u0w = (const float*)d_in[3];
    const float* u0b = (const float*)d_in[4];
    const float* w1w = (const float*)d_in[5];
    const float* w1b = (const float*)d_in[6];
    const float* u1w = (const float*)d_in[7];
    const float* u1b = (const float*)d_in[8];
    float* out = (float*)d_out;

    float* h1ptr = nullptr;
    cudaGetSymbolAddress((void**)&h1ptr, g_h1);

    const size_t H2 = (size_t)BB * TT * HD;        // 8388608
    float* hh = out + H2;                          // [2, B, H]
    float* cc = hh + 2 * BB * HD;                  // [2, B, H]

    const size_t sm0 = (size_t)(16 * HD + 16 * 256 + BB * 256 + BB * HD + 128 + 128 + 16 + 32) * sizeof(float);
    const size_t sm1 = (size_t)(16 * HD + 16 * 512 + BB * 512 + BB * HD + 128 + 128 + 16 + 32) * sizeof(float);
    cudaFuncSetAttribute(lstm_layer_kernel<256>, cudaFuncAttributeMaxDynamicSharedMemorySize, (int)sm0);
    cudaFuncSetAttribute(lstm_layer_kernel<512>, cudaFuncAttributeMaxDynamicSharedMemorySize, (int)sm1);

    reset_bar_kernel<<<1, 1>>>();
    lstm_layer_kernel<256><<<NB, NT, sm0>>>(x, u0w, w0w, u0b, w0b,
                                            h1ptr, hh, cc);
    reset_bar_kernel<<<1, 1>>>();
    lstm_layer_kernel<512><<<NB, NT, sm1>>>(h1ptr, u1w, w1w, u1b, w1b,
                                            out, hh + BB * HD, cc + BB * HD);
}

// round 2
// speedup vs baseline: 1.8655x; 1.8655x over previous
#include <cuda_runtime.h>

#define NB 128   // persistent CTAs (1/SM, all resident -> spin barrier safe)
#define NT 256   // 8 warps
#define TT 2048
#define BB 8
#define HD 512
#define DI 256

// ---------------- device scratch (no cudaMalloc allowed) ----------------
__device__ float g_hA[2 * BB * HD];   // double-buffered h1 broadcast (layer0 out / layer1 in)
__device__ float g_hB[2 * BB * HD];   // double-buffered h2 broadcast (layer1 recurrent)
__device__ unsigned g_count;
__device__ volatile unsigned g_gen;

__global__ void reset_bar_kernel() { g_count = 0u; g_gen = 0u; }

__device__ __forceinline__ float sigm(float x) { return 1.0f / (1.0f + __expf(-x)); }

// Packed dual-FMA: d.lo += a.lo*b.lo, d.hi += a.hi*b.hi  (sm_103a f32x2 pipe)
__device__ __forceinline__ void ffma2(unsigned long long& d, unsigned long long a,
                                      unsigned long long b) {
    asm("fma.rn.f32x2 %0, %1, %2, %0;" : "+l"(d) : "l"(a), "l"(b));
}

// Grid-wide barrier (monotonic generation). All NB CTAs co-resident.
__device__ __forceinline__ void grid_bar(unsigned target) {
    __syncthreads();
    if (threadIdx.x == 0) {
        __threadfence();
        unsigned old = atomicAdd(&g_count, 1u);
        if (old == target * NB - 1u) {
            __threadfence();
            g_gen = target;
        } else {
            while (g_gen < target) { }
        }
    }
    __syncthreads();
}

// Gate dot: acc[r*8+b] (f32x2 k-pair partials) += rows [g4, g4+4) of mat x src[b].
// K split across 32 lanes, vec4 per lane per iter; 64 FFMA2 per iter per warp.
template <int KP>
__device__ __forceinline__ void dot2(unsigned long long* acc, const float* __restrict__ mat,
                                     const float* __restrict__ src, int g4, int lane) {
#pragma unroll
    for (int it = 0; it < KP / 128; it++) {
        const int kb = it * 128 + lane * 4;
        ulonglong2 m[4];
#pragma unroll
        for (int r = 0; r < 4; r++)
            m[r] = *(const ulonglong2*)(mat + (g4 + r) * KP + kb);
#pragma unroll
        for (int b = 0; b < 8; b++) {
            ulonglong2 v = *(const ulonglong2*)(src + b * KP + kb);
#pragma unroll
            for (int r = 0; r < 4; r++) {
                ffma2(acc[r * 8 + b], m[r].x, v.x);
                ffma2(acc[r * 8 + b], m[r].y, v.y);
            }
        }
    }
}

// Fused 2-layer wavefront: period p runs layer0 step p and layer1 step p-1.
// CTA owns hidden columns [j0, j0+4) of BOTH layers; warps 0-3 = layer0 gates,
// warps 4-7 = layer1 gates (each warp reduces the full K -> no partial combine).
__global__ void __launch_bounds__(NT, 1) lstm_fused_kernel(
    const float* __restrict__ x,
    const float* __restrict__ u0W, const float* __restrict__ w0W,
    const float* __restrict__ u0b, const float* __restrict__ w0b,
    const float* __restrict__ u1W, const float* __restrict__ w1W,
    const float* __restrict__ u1b, const float* __restrict__ w1b,
    float* __restrict__ h2seq, float* __restrict__ hh, float* __restrict__ cc)
{
    extern __shared__ float sm[];
    float* sU0    = sm;                  // 16*512
    float* sW0    = sU0 + 16 * HD;       // 16*256
    float* sU1    = sW0 + 16 * DI;       // 16*512
    float* sW1    = sU1 + 16 * HD;       // 16*512
    float* sA     = sW1 + 16 * HD;       // 8*512  h1 stage (L0 recurrent + L1 input)
    float* sB     = sA + BB * HD;        // 8*512  h2 stage (L1 recurrent)
    float* sX     = sB + BB * HD;        // 8*256  x stage
    float* sGates = sX + BB * DI;        // 8*32
    float* sBias  = sGates + 256;        // 32
    float* sC     = sBias + 32;          // 64 (persistent cells: [0:32) L0, [32:64) L1)

    const int tid  = threadIdx.x;
    const int j0   = blockIdx.x * 4;
    const int w    = tid >> 5;
    const int lane = tid & 31;

    // ---- resident weight slices (rows gate*H + j0 + jl, local r = gate*4+jl) ----
    for (int idx = tid; idx < 16 * HD; idx += NT) {
        int r = idx >> 9, k = idx & (HD - 1);
        int row = (r >> 2) * HD + j0 + (r & 3);
        sU0[idx] = u0W[row * HD + k];
        sU1[idx] = u1W[row * HD + k];
        sW1[idx] = w1W[row * HD + k];
    }
    for (int idx = tid; idx < 16 * DI; idx += NT) {
        int r = idx >> 8, k = idx & (DI - 1);
        int row = (r >> 2) * HD + j0 + (r & 3);
        sW0[idx] = w0W[row * DI + k];
    }
    if (tid < 32) {
        int r = tid & 15;
        int row = (r >> 2) * HD + j0 + (r & 3);
        sBias[tid] = (tid < 16) ? (u0b[row] + w0b[row]) : (u1b[row] + w1b[row]);
    }
    if (tid < 64) sC[tid] = 0.0f;
    if (tid < 32) {
        int jl = tid >> 3, b = tid & 7;
        g_hA[b * HD + j0 + jl] = 0.0f;   // h1(-1) in buffer 0
        g_hB[b * HD + j0 + jl] = 0.0f;   // h2(-1) in buffer 0
    }
    grid_bar(1);

    for (int p = 0; p <= TT; p++) {
        // ---- stage broadcasts: sA <- hA[p&1] (h1(p-1)); sB <- hB[(p+1)&1] (h2(p-2)) ----
        {
            const float4* a4 = (const float4*)(g_hA + (p & 1) * (BB * HD));
            const float4* b4 = (const float4*)(g_hB + ((p + 1) & 1) * (BB * HD));
            float4* sA4 = (float4*)sA;
            float4* sB4 = (float4*)sB;
            for (int i = tid; i < BB * HD / 4; i += NT) {
                sA4[i] = __ldcg(a4 + i);
                sB4[i] = __ldcg(b4 + i);
            }
            if (p < TT) {
                const float4* x4 = (const float4*)x;
                float4* sX4 = (float4*)sX;
                for (int i = tid; i < BB * DI / 4; i += NT) {
                    int b = i >> 6, d = i & 63;
                    sX4[i] = x4[(b * TT + p) * 64 + d];
                }
            }
        }
        __syncthreads();

        // ---- gate dots: warp = (layer, gate), full-K reduction per warp ----
        unsigned long long acc[32];
#pragma unroll
        for (int j = 0; j < 32; j++) acc[j] = 0ull;
        if (w < 4) {
            if (p < TT) {
                dot2<HD>(acc, sU0, sA, w * 4, lane);
                dot2<DI>(acc, sW0, sX, w * 4, lane);
            }
        } else {
            if (p > 0) {
                dot2<HD>(acc, sU1, sB, (w - 4) * 4, lane);
                dot2<HD>(acc, sW1, sA, (w - 4) * 4, lane);
            }
        }

        // ---- horizontal add of f32x2 halves, then 31-shuffle reduce-scatter ----
        float av[32];
#pragma unroll
        for (int j = 0; j < 32; j++) {
            unsigned lo, hi;
            asm("mov.b64 {%0,%1}, %2;" : "=r"(lo), "=r"(hi) : "l"(acc[j]));
            av[j] = __uint_as_float(lo) + __uint_as_float(hi);
        }
#pragma unroll
        for (int m = 16; m > 0; m >>= 1) {
            const bool hi = (lane & m) != 0;
#pragma unroll
            for (int j = 0; j < m; j++) {
                float sendv = hi ? av[j] : av[j + m];
                float other = __shfl_xor_sync(0xffffffffu, sendv, m);
                av[j] = (hi ? av[j + m] : av[j]) + other;
            }
        }
        sGates[w * 32 + lane] = av[0] + sBias[w * 4 + (lane >> 3)];
        __syncthreads();

        // ---- layer0 cell update (warp 0), step t0 = p ----
        if (w == 0 && p < TT) {
            const int jl = lane >> 3, b = lane & 7, jg = j0 + jl;
            float iv = sigm(sGates[lane]);
            float fv = sigm(sGates[32 + lane]);
            float gv = tanhf(sGates[64 + lane]);
            float ov = sigm(sGates[96 + lane]);
            float c = fv * sC[lane] + iv * gv;
            sC[lane] = c;
            float h = ov * fmaxf(c, 0.0f);
            g_hA[((p + 1) & 1) * (BB * HD) + b * HD + jg] = h;
            if (p == TT - 1) { hh[b * HD + jg] = h; cc[b * HD + jg] = c; }
        }
        // ---- layer1 cell update (warp 4), step t1 = p-1 ----
        if (w == 4 && p > 0) {
            const int t1 = p - 1;
            const int jl = lane >> 3, b = lane & 7, jg = j0 + jl;
            float iv = sigm(sGates[128 + lane]);
            float fv = sigm(sGates[160 + lane]);
            float gv = tanhf(sGates[192 + lane]);
            float ov = sigm(sGates[224 + lane]);
            float c = fv * sC[32 + lane] + iv * gv;
            sC[32 + lane] = c;
            float h = ov * fmaxf(c, 0.0f);
            g_hB[(p & 1) * (BB * HD) + b * HD + jg] = h;
            h2seq[(b * TT + t1) * HD + jg] = h;
            if (t1 == TT - 1) {
                hh[BB * HD + b * HD + jg] = h;
                cc[BB * HD + b * HD + jg] = c;
            }
        }
        grid_bar((unsigned)(p + 2));
    }
}

// ---------------- host launch ----------------
extern "C" void kernel_launch(void* const* d_in, const int* in_sizes, int n_in,
                              void* d_out, int out_size) {
    (void)in_sizes; (void)n_in; (void)out_size;
    const float* x   = (const float*)d_in[0];
    const float* w0w = (const float*)d_in[1];
    const float* w0b = (const float*)d_in[2];
    const float* u0w = (const float*)d_in[3];
    const float* u0b = (const float*)d_in[4];
    const float* w1w = (const float*)d_in[5];
    const float* w1b = (const float*)d_in[6];
    const float* u1w = (const float*)d_in[7];
    const float* u1b = (const float*)d_in[8];
    float* out = (float*)d_out;

    const size_t H2 = (size_t)BB * TT * HD;   // h2 sequence elements
    float* hh = out + H2;                     // [2, B, H]
    float* cc = hh + 2 * BB * HD;             // [2, B, H]

    const size_t smem = (size_t)(16 * HD * 3 + 16 * DI + 2 * BB * HD + BB * DI
                                 + 256 + 32 + 64) * sizeof(float);  // ~157 KB
    cudaFuncSetAttribute(lstm_fused_kernel, cudaFuncAttributeMaxDynamicSharedMemorySize,
                         (int)smem);

    reset_bar_kernel<<<1, 1>>>();
    lstm_fused_kernel<<<NB, NT, smem>>>(x, u0w, w0w, u0b, w0b,
                                        u1w, w1w, u1b, w1b,
                                        out, hh, cc);
}